// round 9
// baseline (speedup 1.0000x reference)
#include <cuda_runtime.h>
#include <cuda_bf16.h>
#include <cstdint>

// ===================== problem constants =====================
static constexpr int GM = 4096, GN = 4096, GK = 4096;

// GEMM tiling: CTA 128x128, K-stage 64, fused BFP quantization.
static constexpr int BM = 128;
static constexpr int BN = 128;
static constexpr int BK = 64;
static constexpr int KTILES = GK / BK;            // 64

static constexpr int TILE_BYTES = 128 * BK * 2;   // bf16 tile: 16384
static constexpr int BUF_BYTES  = 2 * TILE_BYTES; // A + B = 32768
static constexpr int SMEM_TOTAL = 2 * BUF_BYTES;  // double buffer = 65536

// ===================== PTX helpers =====================
__device__ __forceinline__ uint32_t smem_u32(const void* p) {
    uint32_t a;
    asm("{ .reg .u64 t; cvta.to.shared.u64 t, %1; cvt.u32.u64 %0, t; }" : "=r"(a) : "l"(p));
    return a;
}

#define LDM_X4(r0, r1, r2, r3, addr) \
    asm volatile("ldmatrix.sync.aligned.m8n8.x4.shared.b16 {%0,%1,%2,%3}, [%4];" \
                 : "=r"(r0), "=r"(r1), "=r"(r2), "=r"(r3) : "r"(addr))

#define MMA16816(d0, d1, d2, d3, a0, a1, a2, a3, b0, b1) \
    asm volatile( \
        "mma.sync.aligned.m16n8k16.row.col.f32.bf16.bf16.f32 " \
        "{%0,%1,%2,%3}, {%4,%5,%6,%7}, {%8,%9}, {%0,%1,%2,%3};" \
        : "+f"(d0), "+f"(d1), "+f"(d2), "+f"(d3) \
        : "r"(a0), "r"(a1), "r"(a2), "r"(a3), "r"(b0), "r"(b1))

#define STS128(addr, r0, r1, r2, r3) \
    asm volatile("st.shared.v4.b32 [%0], {%1,%2,%3,%4};" \
                 :: "r"(addr), "r"(r0), "r"(r1), "r"(r2), "r"(r3) : "memory")

// ===================== in-register BFP quantization ========================
// One group of 16 fp32 (held in 4 float4) -> 16 bf16 (8 u32) -> 2x STS.128.
// Exact semantics of the reference: shared exponent floor(log2(max|x|)),
// round-half-even to 8-bit signed mantissa, dequantize. Values q*2^(e-6),
// |q|<=128, are exactly representable in bf16.
__device__ __forceinline__ void quant_group_sts(float4 q0, float4 q1, float4 q2, float4 q3,
                                                uint32_t s0, uint32_t s1) {
    float m = fmaxf(
        fmaxf(fmaxf(fmaxf(fabsf(q0.x), fabsf(q0.y)), fmaxf(fabsf(q0.z), fabsf(q0.w))),
              fmaxf(fmaxf(fabsf(q1.x), fabsf(q1.y)), fmaxf(fabsf(q1.z), fabsf(q1.w)))),
        fmaxf(fmaxf(fmaxf(fabsf(q2.x), fabsf(q2.y)), fmaxf(fabsf(q2.z), fabsf(q2.w))),
              fmaxf(fmaxf(fabsf(q3.x), fabsf(q3.y)), fmaxf(fabsf(q3.z), fabsf(q3.w)))));
    uint32_t mb = __float_as_uint(m);
    int e = (int)(mb >> 23) - 127;                       // exact floor(log2(m)), m normal
    float inv = __uint_as_float((uint32_t)(133 - e) << 23);  // 2^(6-e)
    float scl = __uint_as_float((uint32_t)(121 + e) << 23);  // 2^(e-6)
    if (m == 0.f) { inv = 0.f; scl = 0.f; }

#define QP(dst, fa, fb) do {                                                   \
        float _a = fminf(fmaxf(rintf((fa) * inv), -128.f), 127.f) * scl;       \
        float _b = fminf(fmaxf(rintf((fb) * inv), -128.f), 127.f) * scl;       \
        uint32_t _lo = (uint32_t)__bfloat16_as_ushort(__float2bfloat16(_a));   \
        uint32_t _hi = (uint32_t)__bfloat16_as_ushort(__float2bfloat16(_b));   \
        dst = _lo | (_hi << 16);                                               \
    } while (0)
    uint32_t p0, p1, p2, p3, p4, p5, p6, p7;
    QP(p0, q0.x, q0.y); QP(p1, q0.z, q0.w);
    QP(p2, q1.x, q1.y); QP(p3, q1.z, q1.w);
    QP(p4, q2.x, q2.y); QP(p5, q2.z, q2.w);
    QP(p6, q3.x, q3.y); QP(p7, q3.z, q3.w);
#undef QP
    STS128(s0, p0, p1, p2, p3);
    STS128(s1, p4, p5, p6, p7);
}

// ===================== fused BFP GEMM ======================================
// 256 threads = 8 warps, 4(M) x 2(N); warp tile 32x64; acc 64 f32/thread.
// Per iteration: LDG next fp32 tiles -> MMA current bf16 tiles -> quantize
// loaded regs into the other smem buffer -> syncthreads.
__global__ void __launch_bounds__(256, 1)
bfp_gemm_fused(const float* __restrict__ x, const float* __restrict__ w,
               const float* __restrict__ bias, float* __restrict__ out) {
    extern __shared__ char smem[];
    uint32_t sb = smem_u32(smem);
    int tid = threadIdx.x;
    int wid = tid >> 5;
    int lid = tid & 31;
    int wm = wid & 3;        // M warp: 0..3 (32 rows each)
    int wn = wid >> 2;       // N warp: 0..1 (64 cols each)
    int tile_n = blockIdx.x;
    int tile_m = blockIdx.y;

    // ---- quant-duty mapping: row = tid&127, groups {g0, g0+1} for A and B ----
    int qrow = tid & 127;
    int g0 = (tid >> 7) * 2;                 // 0 or 2
    const float4* aG = (const float4*)x + (size_t)(tile_m * BM + qrow) * (GK / 4);
    const float4* bG = (const float4*)w + (size_t)(tile_n * BN + qrow) * (GK / 4);
    // swizzled STS targets for (qrow, g): o = qrow*128 + g*32, mask = (qrow&7)<<4
    uint32_t q_mask = (uint32_t)(qrow & 7) << 4;
    uint32_t oA0 = (uint32_t)qrow * 128u + (uint32_t)g0 * 32u;
    uint32_t sA00 = oA0 ^ q_mask,        sA01 = (oA0 + 16u) ^ q_mask;
    uint32_t sA10 = (oA0 + 32u) ^ q_mask, sA11 = (oA0 + 48u) ^ q_mask;

    // ---- ldmatrix address components (SW128 => per-row XOR mask) ----
    uint32_t a_kx = (uint32_t)((lid >> 4) << 4);
    int arow0 = wm * 32 + (lid & 15);
    int arow1 = arow0 + 16;
    uint32_t a_ro0 = (uint32_t)arow0 * 128u, a_mk0 = (uint32_t)(arow0 & 7) << 4;
    uint32_t a_ro1 = (uint32_t)arow1 * 128u, a_mk1 = (uint32_t)(arow1 & 7) << 4;

    uint32_t b_kx = (uint32_t)(((lid >> 3) & 1) << 4);
    int brow0 = wn * 64 + ((lid >> 4) & 1) * 8 + (lid & 7);
    uint32_t b_ro0 = (uint32_t)(brow0)      * 128u, b_mk0 = (uint32_t)((brow0)      & 7) << 4;
    uint32_t b_ro1 = (uint32_t)(brow0 + 16) * 128u, b_mk1 = (uint32_t)((brow0 + 16) & 7) << 4;
    uint32_t b_ro2 = (uint32_t)(brow0 + 32) * 128u, b_mk2 = (uint32_t)((brow0 + 32) & 7) << 4;
    uint32_t b_ro3 = (uint32_t)(brow0 + 48) * 128u, b_mk3 = (uint32_t)((brow0 + 48) & 7) << 4;

    float acc[2][8][4];
#pragma unroll
    for (int am = 0; am < 2; am++)
#pragma unroll
        for (int j = 0; j < 8; j++)
#pragma unroll
            for (int c = 0; c < 4; c++) acc[am][j][c] = 0.f;

    // staged fp32 regs for the next tile: [A g0, A g0+1, B g0, B g0+1] x 4 float4
    float4 ra0[4], ra1[4], rb0[4], rb1[4];

    // ---- prologue: load + quantize tile 0 into buffer 0 ----
    {
        const float4* a0p = aG + g0 * 4;
        const float4* b0p = bG + g0 * 4;
#pragma unroll
        for (int i = 0; i < 4; i++) { ra0[i] = a0p[i]; ra1[i] = a0p[4 + i]; }
#pragma unroll
        for (int i = 0; i < 4; i++) { rb0[i] = b0p[i]; rb1[i] = b0p[4 + i]; }
        uint32_t aDst = sb;                       // buffer 0: A at +0
        uint32_t bDst = sb + TILE_BYTES;          //           B at +16KB
        quant_group_sts(ra0[0], ra0[1], ra0[2], ra0[3], aDst + sA00, aDst + sA01);
        quant_group_sts(ra1[0], ra1[1], ra1[2], ra1[3], aDst + sA10, aDst + sA11);
        quant_group_sts(rb0[0], rb0[1], rb0[2], rb0[3], bDst + sA00, bDst + sA01);
        quant_group_sts(rb1[0], rb1[1], rb1[2], rb1[3], bDst + sA10, bDst + sA11);
    }
    __syncthreads();

    // ---- main loop ----
    for (int kt = 0; kt < KTILES; kt++) {
        // issue global loads for tile kt+1 (latency hidden behind MMA below)
        if (kt + 1 < KTILES) {
            const float4* ap = aG + (kt + 1) * 16 + g0 * 4;
            const float4* bp = bG + (kt + 1) * 16 + g0 * 4;
#pragma unroll
            for (int i = 0; i < 4; i++) { ra0[i] = ap[i]; ra1[i] = ap[4 + i]; }
#pragma unroll
            for (int i = 0; i < 4; i++) { rb0[i] = bp[i]; rb1[i] = bp[4 + i]; }
        }

        // MMA over buffer kt&1
        uint32_t aBase = sb + (uint32_t)(kt & 1) * BUF_BYTES;
        uint32_t bBase = aBase + TILE_BYTES;
#pragma unroll
        for (int ks = 0; ks < 4; ks++) {
            uint32_t ko = (uint32_t)ks * 32u;
            uint32_t a00, a01, a02, a03, a10, a11, a12, a13;
            LDM_X4(a00, a01, a02, a03, aBase + a_ro0 + ((ko + a_kx) ^ a_mk0));
            LDM_X4(a10, a11, a12, a13, aBase + a_ro1 + ((ko + a_kx) ^ a_mk1));
            uint32_t b00, b01, b02, b03, b10, b11, b12, b13;
            uint32_t b20, b21, b22, b23, b30, b31, b32, b33;
            LDM_X4(b00, b01, b02, b03, bBase + b_ro0 + ((ko + b_kx) ^ b_mk0));
            LDM_X4(b10, b11, b12, b13, bBase + b_ro1 + ((ko + b_kx) ^ b_mk1));
            LDM_X4(b20, b21, b22, b23, bBase + b_ro2 + ((ko + b_kx) ^ b_mk2));
            LDM_X4(b30, b31, b32, b33, bBase + b_ro3 + ((ko + b_kx) ^ b_mk3));

#define MMA_ROW(am, A0, A1, A2, A3)                                                          \
            MMA16816(acc[am][0][0], acc[am][0][1], acc[am][0][2], acc[am][0][3], A0, A1, A2, A3, b00, b01); \
            MMA16816(acc[am][1][0], acc[am][1][1], acc[am][1][2], acc[am][1][3], A0, A1, A2, A3, b02, b03); \
            MMA16816(acc[am][2][0], acc[am][2][1], acc[am][2][2], acc[am][2][3], A0, A1, A2, A3, b10, b11); \
            MMA16816(acc[am][3][0], acc[am][3][1], acc[am][3][2], acc[am][3][3], A0, A1, A2, A3, b12, b13); \
            MMA16816(acc[am][4][0], acc[am][4][1], acc[am][4][2], acc[am][4][3], A0, A1, A2, A3, b20, b21); \
            MMA16816(acc[am][5][0], acc[am][5][1], acc[am][5][2], acc[am][5][3], A0, A1, A2, A3, b22, b23); \
            MMA16816(acc[am][6][0], acc[am][6][1], acc[am][6][2], acc[am][6][3], A0, A1, A2, A3, b30, b31); \
            MMA16816(acc[am][7][0], acc[am][7][1], acc[am][7][2], acc[am][7][3], A0, A1, A2, A3, b32, b33)

            MMA_ROW(0, a00, a01, a02, a03);
            MMA_ROW(1, a10, a11, a12, a13);
#undef MMA_ROW
        }

        // quantize staged regs into the other buffer
        if (kt + 1 < KTILES) {
            uint32_t aDst = sb + (uint32_t)((kt + 1) & 1) * BUF_BYTES;
            uint32_t bDst = aDst + TILE_BYTES;
            quant_group_sts(ra0[0], ra0[1], ra0[2], ra0[3], aDst + sA00, aDst + sA01);
            quant_group_sts(ra1[0], ra1[1], ra1[2], ra1[3], aDst + sA10, aDst + sA11);
            quant_group_sts(rb0[0], rb0[1], rb0[2], rb0[3], bDst + sA00, bDst + sA01);
            quant_group_sts(rb1[0], rb1[1], rb1[2], rb1[3], bDst + sA10, bDst + sA11);
        }
        __syncthreads();
    }

    // ---- epilogue ----
    int col0 = tile_n * BN + wn * 64 + (lid & 3) * 2;
#pragma unroll
    for (int am = 0; am < 2; am++) {
        int row0 = tile_m * BM + wm * 32 + am * 16 + (lid >> 2);
#pragma unroll
        for (int j = 0; j < 8; j++) {
            int col = col0 + j * 8;
            float b0 = bias[col], b1 = bias[col + 1];
            float2 v0 = make_float2(acc[am][j][0] + b0, acc[am][j][1] + b1);
            float2 v1 = make_float2(acc[am][j][2] + b0, acc[am][j][3] + b1);
            *(float2*)(out + (size_t)row0 * GN + col)       = v0;
            *(float2*)(out + (size_t)(row0 + 8) * GN + col) = v1;
        }
    }
}

// ===================== launch =====================
extern "C" void kernel_launch(void* const* d_in, const int* in_sizes, int n_in,
                              void* d_out, int out_size) {
    const float* x    = (const float*)d_in[0];   // [4096, 4096]
    const float* w    = (const float*)d_in[1];   // [4096, 4096]
    const float* bias = (const float*)d_in[2];   // [4096]
    float* out = (float*)d_out;                  // [4096, 4096]

    (void)in_sizes; (void)n_in; (void)out_size;

    static bool attr_done = false;
    if (!attr_done) {
        cudaFuncSetAttribute(bfp_gemm_fused,
                             cudaFuncAttributeMaxDynamicSharedMemorySize, SMEM_TOTAL);
        attr_done = true;
    }

    dim3 grid(GN / BN, GM / BM);  // (32, 32), x fastest => B-tile L2 reuse
    bfp_gemm_fused<<<grid, 256, SMEM_TOTAL>>>(x, w, bias, out);
}

// round 10
// speedup vs baseline: 2.5146x; 2.5146x over previous
#include <cuda_runtime.h>
#include <cuda_bf16.h>
#include <cstdint>

// ===================== problem constants =====================
static constexpr int GM = 4096, GN = 4096, GK = 4096;

// GEMM tiling: CTA 128x128, K-stage 64, fused BFP quantization.
static constexpr int BM = 128;
static constexpr int BN = 128;
static constexpr int BK = 64;
static constexpr int KTILES = GK / BK;            // 64

static constexpr int TILE_BYTES = 128 * BK * 2;   // bf16 tile: 16384
static constexpr int BUF_BYTES  = 2 * TILE_BYTES; // A + B = 32768
static constexpr int SMEM_TOTAL = 2 * BUF_BYTES;  // double buffer = 65536

// ===================== PTX helpers =====================
__device__ __forceinline__ uint32_t smem_u32(const void* p) {
    uint32_t a;
    asm("{ .reg .u64 t; cvta.to.shared.u64 t, %1; cvt.u32.u64 %0, t; }" : "=r"(a) : "l"(p));
    return a;
}

#define LDM_X4(r0, r1, r2, r3, addr) \
    asm volatile("ldmatrix.sync.aligned.m8n8.x4.shared.b16 {%0,%1,%2,%3}, [%4];" \
                 : "=r"(r0), "=r"(r1), "=r"(r2), "=r"(r3) : "r"(addr))

#define MMA16816(d0, d1, d2, d3, a0, a1, a2, a3, b0, b1) \
    asm volatile( \
        "mma.sync.aligned.m16n8k16.row.col.f32.bf16.bf16.f32 " \
        "{%0,%1,%2,%3}, {%4,%5,%6,%7}, {%8,%9}, {%0,%1,%2,%3};" \
        : "+f"(d0), "+f"(d1), "+f"(d2), "+f"(d3) \
        : "r"(a0), "r"(a1), "r"(a2), "r"(a3), "r"(b0), "r"(b1))

// ===================== fused BFP GEMM ======================================
// 256 threads = 8 warps, 4(M) x 2(N); warp tile 32x64; acc 64 f32/thread.
//
// COALESCED quant-duty mapping: thread t -> (row t>>4, float4-col t&15).
// A warp's 16-lane half covers 256 contiguous bytes of one row -> 4 L1 lines
// per LDG.128 (vs 32 for the old per-thread-row mapping). Each BFP group of
// 16 floats is held by an aligned quad of lanes; group max via 2x shfl.xor.
//
// Quantization (exact round-half-even, matches jnp.round):
//   x*inv is EXACT (inv = 2^(6-e)); fmaf(x, inv, 1.5*2^23) rounds the exact
//   value half-even to integer ulp; upper clamp min(.,magic+127) (lower bound
//   -128 is unreachable & allowed); subtract magic (exact); multiply by
//   scl = 2^(e-6). Values q*2^(e-6), |q|<=127|128 are exact in bf16.
__global__ void __launch_bounds__(256, 1)
bfp_gemm_fused(const float* __restrict__ x, const float* __restrict__ w,
               const float* __restrict__ bias, float* __restrict__ out) {
    extern __shared__ char smem[];
    uint32_t sb = smem_u32(smem);
    int tid = threadIdx.x;
    int wid = tid >> 5;
    int lid = tid & 31;
    int wm = wid & 3;        // M warp: 0..3 (32 rows each)
    int wn = wid >> 2;       // N warp: 0..1 (64 cols each)
    int tile_n = blockIdx.x;
    int tile_m = blockIdx.y;

    // ---- coalesced quant-duty mapping ----
    int qr = tid >> 4;                 // base row 0..15 (thread covers +16i, i<8)
    int qc = tid & 15;                 // float4 column within the 64-float K-slab
    const float4* aP = (const float4*)x + (size_t)(tile_m * BM + qr) * (GK / 4) + qc;
    const float4* bP = (const float4*)w + (size_t)(tile_n * BN + qr) * (GK / 4) + qc;
    const size_t rstep = (size_t)16 * (GK / 4);   // +16 rows, in float4 units
    // bf16 smem target for (row qr+16i, float4 qc): o = row*128 + qc*8, XOR
    // swizzle mask ((row&7)<<4) is invariant in i since 16i = 0 (mod 8).
    uint32_t sts0 = ((uint32_t)(qr * 128 + qc * 8)) ^ ((uint32_t)(qr & 7) << 4);

    // ---- ldmatrix address components (SW128 => per-row XOR mask) ----
    uint32_t a_kx = (uint32_t)((lid >> 4) << 4);
    int arow0 = wm * 32 + (lid & 15);
    int arow1 = arow0 + 16;
    uint32_t a_ro0 = (uint32_t)arow0 * 128u, a_mk0 = (uint32_t)(arow0 & 7) << 4;
    uint32_t a_ro1 = (uint32_t)arow1 * 128u, a_mk1 = (uint32_t)(arow1 & 7) << 4;

    uint32_t b_kx = (uint32_t)(((lid >> 3) & 1) << 4);
    int brow0 = wn * 64 + ((lid >> 4) & 1) * 8 + (lid & 7);
    uint32_t b_ro0 = (uint32_t)(brow0)      * 128u, b_mk0 = (uint32_t)((brow0)      & 7) << 4;
    uint32_t b_ro1 = (uint32_t)(brow0 + 16) * 128u, b_mk1 = (uint32_t)((brow0 + 16) & 7) << 4;
    uint32_t b_ro2 = (uint32_t)(brow0 + 32) * 128u, b_mk2 = (uint32_t)((brow0 + 32) & 7) << 4;
    uint32_t b_ro3 = (uint32_t)(brow0 + 48) * 128u, b_mk3 = (uint32_t)((brow0 + 48) & 7) << 4;

    float acc[2][8][4];
#pragma unroll
    for (int am = 0; am < 2; am++)
#pragma unroll
        for (int j = 0; j < 8; j++)
#pragma unroll
            for (int c = 0; c < 4; c++) acc[am][j][c] = 0.f;

    float4 ra[8], rb[8];   // staged fp32 (fully unrolled -> registers)

#define LOAD_TILE(kt4) do {                                                    \
        _Pragma("unroll")                                                      \
        for (int i = 0; i < 8; i++) ra[i] = aP[(kt4) + (size_t)i * rstep];     \
        _Pragma("unroll")                                                      \
        for (int i = 0; i < 8; i++) rb[i] = bP[(kt4) + (size_t)i * rstep];     \
    } while (0)

#define QSTORE(arr, dstBase) do {                                              \
        _Pragma("unroll")                                                      \
        for (int i = 0; i < 8; i++) {                                          \
            float4 v = arr[i];                                                 \
            float m4 = fmaxf(fmaxf(fabsf(v.x), fabsf(v.y)),                    \
                             fmaxf(fabsf(v.z), fabsf(v.w)));                   \
            m4 = fmaxf(m4, __shfl_xor_sync(0xffffffffu, m4, 1));               \
            m4 = fmaxf(m4, __shfl_xor_sync(0xffffffffu, m4, 2));               \
            uint32_t mb = __float_as_uint(m4);                                 \
            int e = (int)(mb >> 23) - 127;                                     \
            float inv = __uint_as_float((uint32_t)(133 - e) << 23);            \
            float scl = __uint_as_float((uint32_t)(121 + e) << 23);            \
            float q0 = (fminf(fmaf(v.x, inv, 12582912.f), 12583039.f) - 12582912.f) * scl; \
            float q1 = (fminf(fmaf(v.y, inv, 12582912.f), 12583039.f) - 12582912.f) * scl; \
            float q2 = (fminf(fmaf(v.z, inv, 12582912.f), 12583039.f) - 12582912.f) * scl; \
            float q3 = (fminf(fmaf(v.w, inv, 12582912.f), 12583039.f) - 12582912.f) * scl; \
            uint32_t p0, p1;                                                   \
            asm("cvt.rn.satfinite.bf16x2.f32 %0, %1, %2;" : "=r"(p0) : "f"(q1), "f"(q0)); \
            asm("cvt.rn.satfinite.bf16x2.f32 %0, %1, %2;" : "=r"(p1) : "f"(q3), "f"(q2)); \
            asm volatile("st.shared.v2.b32 [%0], {%1,%2};"                     \
                         :: "r"((dstBase) + sts0 + (uint32_t)(i * 2048)),      \
                            "r"(p0), "r"(p1) : "memory");                      \
        }                                                                      \
    } while (0)

    // ---- prologue: load + quantize tile 0 into buffer 0 ----
    LOAD_TILE(0);
    QSTORE(ra, sb);
    QSTORE(rb, sb + TILE_BYTES);
    __syncthreads();

    // ---- main loop ----
    for (int kt = 0; kt < KTILES; kt++) {
        if (kt + 1 < KTILES) LOAD_TILE((size_t)(kt + 1) * 16);

        uint32_t aBase = sb + (uint32_t)(kt & 1) * BUF_BYTES;
        uint32_t bBase = aBase + TILE_BYTES;
#pragma unroll
        for (int ks = 0; ks < 4; ks++) {
            uint32_t ko = (uint32_t)ks * 32u;
            uint32_t a00, a01, a02, a03, a10, a11, a12, a13;
            LDM_X4(a00, a01, a02, a03, aBase + a_ro0 + ((ko + a_kx) ^ a_mk0));
            LDM_X4(a10, a11, a12, a13, aBase + a_ro1 + ((ko + a_kx) ^ a_mk1));
            uint32_t b00, b01, b02, b03, b10, b11, b12, b13;
            uint32_t b20, b21, b22, b23, b30, b31, b32, b33;
            LDM_X4(b00, b01, b02, b03, bBase + b_ro0 + ((ko + b_kx) ^ b_mk0));
            LDM_X4(b10, b11, b12, b13, bBase + b_ro1 + ((ko + b_kx) ^ b_mk1));
            LDM_X4(b20, b21, b22, b23, bBase + b_ro2 + ((ko + b_kx) ^ b_mk2));
            LDM_X4(b30, b31, b32, b33, bBase + b_ro3 + ((ko + b_kx) ^ b_mk3));

#define MMA_ROW(am, A0, A1, A2, A3)                                                          \
            MMA16816(acc[am][0][0], acc[am][0][1], acc[am][0][2], acc[am][0][3], A0, A1, A2, A3, b00, b01); \
            MMA16816(acc[am][1][0], acc[am][1][1], acc[am][1][2], acc[am][1][3], A0, A1, A2, A3, b02, b03); \
            MMA16816(acc[am][2][0], acc[am][2][1], acc[am][2][2], acc[am][2][3], A0, A1, A2, A3, b10, b11); \
            MMA16816(acc[am][3][0], acc[am][3][1], acc[am][3][2], acc[am][3][3], A0, A1, A2, A3, b12, b13); \
            MMA16816(acc[am][4][0], acc[am][4][1], acc[am][4][2], acc[am][4][3], A0, A1, A2, A3, b20, b21); \
            MMA16816(acc[am][5][0], acc[am][5][1], acc[am][5][2], acc[am][5][3], A0, A1, A2, A3, b22, b23); \
            MMA16816(acc[am][6][0], acc[am][6][1], acc[am][6][2], acc[am][6][3], A0, A1, A2, A3, b30, b31); \
            MMA16816(acc[am][7][0], acc[am][7][1], acc[am][7][2], acc[am][7][3], A0, A1, A2, A3, b32, b33)

            MMA_ROW(0, a00, a01, a02, a03);
            MMA_ROW(1, a10, a11, a12, a13);
#undef MMA_ROW
        }

        if (kt + 1 < KTILES) {
            uint32_t aDst = sb + (uint32_t)((kt + 1) & 1) * BUF_BYTES;
            QSTORE(ra, aDst);
            QSTORE(rb, aDst + TILE_BYTES);
        }
        __syncthreads();
    }

#undef LOAD_TILE
#undef QSTORE

    // ---- epilogue ----
    int col0 = tile_n * BN + wn * 64 + (lid & 3) * 2;
#pragma unroll
    for (int am = 0; am < 2; am++) {
        int row0 = tile_m * BM + wm * 32 + am * 16 + (lid >> 2);
#pragma unroll
        for (int j = 0; j < 8; j++) {
            int col = col0 + j * 8;
            float b0 = bias[col], b1 = bias[col + 1];
            float2 v0 = make_float2(acc[am][j][0] + b0, acc[am][j][1] + b1);
            float2 v1 = make_float2(acc[am][j][2] + b0, acc[am][j][3] + b1);
            *(float2*)(out + (size_t)row0 * GN + col)       = v0;
            *(float2*)(out + (size_t)(row0 + 8) * GN + col) = v1;
        }
    }
}

// ===================== launch =====================
extern "C" void kernel_launch(void* const* d_in, const int* in_sizes, int n_in,
                              void* d_out, int out_size) {
    const float* x    = (const float*)d_in[0];   // [4096, 4096]
    const float* w    = (const float*)d_in[1];   // [4096, 4096]
    const float* bias = (const float*)d_in[2];   // [4096]
    float* out = (float*)d_out;                  // [4096, 4096]

    (void)in_sizes; (void)n_in; (void)out_size;

    static bool attr_done = false;
    if (!attr_done) {
        cudaFuncSetAttribute(bfp_gemm_fused,
                             cudaFuncAttributeMaxDynamicSharedMemorySize, SMEM_TOTAL);
        attr_done = true;
    }

    dim3 grid(GN / BN, GM / BM);  // (32, 32), x fastest => B-tile L2 reuse
    bfp_gemm_fused<<<grid, 256, SMEM_TOTAL>>>(x, w, bias, out);
}